// round 8
// baseline (speedup 1.0000x reference)
#include <cuda_runtime.h>

#define D 128
#define NMAX 50000

typedef unsigned long long u64;

// ---- scratch (static device globals; no allocations allowed) ----
__device__ float g_A  [(size_t)NMAX * D];   // h @ W1a.T
__device__ float g_B  [(size_t)NMAX * D];   // h @ W1b.T
__device__ float g_agg[(size_t)NMAX * D];   // scatter-add target
__device__ float g_T  [(size_t)NMAX * D];   // silu(u_in @ U1.T + c1)
__device__ int   g_is64;                    // edge_index dtype flag

// k-major weight copies: gWT[k*128 + d] = W[d][k]
__device__ float g_W1Ta[128 * 128];
__device__ float g_W1Tb[128 * 128];
__device__ float g_W2T [128 * 128];
__device__ float g_U1Ta[128 * 128];
__device__ float g_U1Tb[128 * 128];
__device__ float g_U2T [128 * 128];

__device__ __forceinline__ float silu_f(float v) {
    return v / (1.0f + __expf(-v));
}
__device__ __forceinline__ u64 pack2(float lo, float hi) {
    u64 r;
    asm("mov.b64 %0, {%1, %2};" : "=l"(r) : "f"(lo), "f"(hi));
    return r;
}
__device__ __forceinline__ float2 unpack2(u64 v) {
    float2 r;
    asm("mov.b64 {%0, %1}, %2;" : "=f"(r.x), "=f"(r.y) : "l"(v));
    return r;
}
__device__ __forceinline__ void ffma2(u64& d, u64 a, u64 b) {
    asm("fma.rn.f32x2 %0, %1, %2, %0;" : "+l"(d) : "l"(a), "l"(b));
}
__device__ __forceinline__ void red_v4(float* p, float a, float b, float c, float d) {
    asm volatile("red.global.add.v4.f32 [%0], {%1, %2, %3, %4};"
                 :: "l"(p), "f"(a), "f"(b), "f"(c), "f"(d) : "memory");
}

// ----------------------------------------------------------------------------
// All six 128x128 weight transposes in one kernel; destination symbols are
// referenced in DEVICE code (passing __device__ symbols as host-side kernel
// args is UB — that was the round-5 bug).
// blockIdx.z selects the matrix; out[k*128 + d] = in[d*ldin + off + k].
// ----------------------------------------------------------------------------
__global__ void transpose_all_kernel(const float* __restrict__ W1,
                                     const float* __restrict__ W2,
                                     const float* __restrict__ U1,
                                     const float* __restrict__ U2)
{
    const float* in; float* out; int ldin, off;
    switch (blockIdx.z) {
        case 0: in = W1; out = g_W1Ta; ldin = 257; off = 0;   break;
        case 1: in = W1; out = g_W1Tb; ldin = 257; off = 128; break;
        case 2: in = W2; out = g_W2T;  ldin = 128; off = 0;   break;
        case 3: in = U1; out = g_U1Ta; ldin = 256; off = 0;   break;
        case 4: in = U1; out = g_U1Tb; ldin = 256; off = 128; break;
        default: in = U2; out = g_U2T; ldin = 128; off = 0;   break;
    }
    __shared__ float t[32][33];
    int kb = blockIdx.x * 32, db = blockIdx.y * 32;
    int tx = threadIdx.x, ty = threadIdx.y;
    for (int j = ty; j < 32; j += 8)
        t[j][tx] = in[(size_t)(db + j) * ldin + off + kb + tx];
    __syncthreads();
    for (int j = ty; j < 32; j += 8)
        out[(size_t)(kb + j) * 128 + db + tx] = t[tx][j];
}

// ----------------------------------------------------------------------------
__global__ void detect_idx_kernel(const int* __restrict__ ei32, int E)
{
    __shared__ int any_nz;
    if (threadIdx.x == 0) any_nz = 0;
    __syncthreads();
    int samples = min(1024, E);
    for (int i = threadIdx.x; i < samples; i += blockDim.x)
        if (ei32[2 * i + 1] != 0) any_nz = 1;
    __syncthreads();
    if (threadIdx.x == 0) g_is64 = (any_nz == 0) ? 1 : 0;
}

__device__ __forceinline__ void load_edge(const void* ei, int E, int e, int is64,
                                          int& s, int& r)
{
    if (is64) {
        s = (int)((const long long*)ei)[e];
        r = (int)((const long long*)ei)[(size_t)E + e];
    } else {
        s = ((const int*)ei)[e];
        r = ((const int*)ei)[E + e];
    }
}

// ----------------------------------------------------------------------------
// 8x8 register-tiled fp32x2 GEMM over a [128 x 128] activation tile in smem
// (padded stride 132) and a k-major weight matrix in GLOBAL memory (L1-resident
// after first touch; identical for all CTAs).
// Thread (tx,ty): rows {ty*4..+3, 64+ty*4..+3}, cols {tx*4..+3, 64+tx*4..+3}.
// ----------------------------------------------------------------------------
__device__ __forceinline__ void gemm_tile_g(const float (*__restrict__ XE)[132],
                                            const float* __restrict__ WG,
                                            u64 (&acc2)[8][4], int tx, int ty)
{
    const int eb = ty * 4, db = tx * 4;
    #pragma unroll 4
    for (int k = 0; k < 128; ++k) {
        const float* wr = WG + k * 128;
        ulonglong2 w0 = *(const ulonglong2*)(wr + db);
        ulonglong2 w1 = *(const ulonglong2*)(wr + 64 + db);
        u64 wv[4] = {w0.x, w0.y, w1.x, w1.y};
        u64 xa2[8];
        #pragma unroll
        for (int i = 0; i < 4; ++i) {
            float x0 = XE[eb + i][k];
            float x1 = XE[64 + eb + i][k];
            xa2[i]     = pack2(x0, x0);
            xa2[4 + i] = pack2(x1, x1);
        }
        #pragma unroll
        for (int i = 0; i < 8; ++i)
            #pragma unroll
            for (int jp = 0; jp < 4; ++jp)
                ffma2(acc2[i][jp], xa2[i], wv[jp]);
    }
}

// ----------------------------------------------------------------------------
__global__ void zero_agg_kernel(int n4) {
    int i = blockIdx.x * blockDim.x + threadIdx.x;
    if (i < n4) ((float4*)g_agg)[i] = make_float4(0.f, 0.f, 0.f, 0.f);
}

// ----------------------------------------------------------------------------
// A = h @ W1[:, :128].T ; B = h @ W1[:, 128:256].T   (blockIdx.y selects half)
// ----------------------------------------------------------------------------
__global__ __launch_bounds__(256, 2)
void nodeAB_kernel(const float* __restrict__ h, int N)
{
    extern __shared__ float sm[];
    float (*XE)[132] = (float (*)[132])sm;                 // 128 x 132

    const int tid  = threadIdx.x;
    const int n0   = blockIdx.x * 128;
    const int half = blockIdx.y;
    const float* WG = half ? g_W1Tb : g_W1Ta;

    for (int i = tid; i < 128 * 32; i += 256) {
        int e = i >> 5, d4 = (i & 31) << 2;
        int n = n0 + e;
        float4 v = make_float4(0.f, 0.f, 0.f, 0.f);
        if (n < N) v = *(const float4*)(h + (size_t)n * D + d4);
        *(float4*)&XE[e][d4] = v;
    }
    __syncthreads();

    const int tx = tid & 15, ty = tid >> 4;
    u64 acc2[8][4];
    #pragma unroll
    for (int i = 0; i < 8; ++i)
        #pragma unroll
        for (int j = 0; j < 4; ++j) acc2[i][j] = 0ull;

    gemm_tile_g(XE, WG, acc2, tx, ty);

    float* outp = half ? g_B : g_A;
    #pragma unroll
    for (int i = 0; i < 8; ++i) {
        int e = (i < 4) ? (ty * 4 + i) : (64 + ty * 4 + i - 4);
        int n = n0 + e;
        if (n >= N) continue;
        float2 p0 = unpack2(acc2[i][0]), p1 = unpack2(acc2[i][1]);
        float2 p2 = unpack2(acc2[i][2]), p3 = unpack2(acc2[i][3]);
        *(float4*)(outp + (size_t)n * D + tx * 4)      = make_float4(p0.x, p0.y, p1.x, p1.y);
        *(float4*)(outp + (size_t)n * D + 64 + tx * 4) = make_float4(p2.x, p2.y, p3.x, p3.y);
    }
}

// ----------------------------------------------------------------------------
// Edge kernel (128 edges/block, 256 threads, 2 CTAs/SM):
//   x[e] = silu(A[s] + B[r] + dist*w1c + b1)   (layer-1 collapsed)
//   y[e] = silu(x[e] @ W2.T + b2)              (8x8 fp32x2 GEMM, W from global)
//   red.global.add.v4(agg[r], y[e])
// ----------------------------------------------------------------------------
__global__ __launch_bounds__(256, 2)
void edge_kernel(const float* __restrict__ coords,
                 const void* __restrict__ ei,
                 const float* __restrict__ W1,
                 const float* __restrict__ b1,
                 const float* __restrict__ b2,
                 int E)
{
    extern __shared__ float sm[];
    float (*XE)[132] = (float (*)[132])sm;                   // 128 x 132
    float* sw1c  = sm + 128 * 132;                           // 128
    float* sb1   = sw1c + 128;                               // 128
    float* sb2   = sb1 + 128;                                // 128
    float* sdist = sb2 + 128;                                // 128
    int*   sr    = (int*)(sdist + 128);                      // 128
    int*   ss    = sr + 128;                                 // 128

    const int tid = threadIdx.x;
    const int e0  = blockIdx.x * 128;
    const int is64 = g_is64;

    if (tid < 128) {
        sb1[tid]  = b1[tid];
        sb2[tid]  = b2[tid];
        sw1c[tid] = W1[tid * 257 + 256];
    } else {
        int t = tid - 128;
        int e = e0 + t;
        if (e < E) {
            int s, r;
            load_edge(ei, E, e, is64, s, r);
            ss[t] = s;
            sr[t] = r;
            float dx = coords[s * 3 + 0] - coords[r * 3 + 0];
            float dy = coords[s * 3 + 1] - coords[r * 3 + 1];
            float dz = coords[s * 3 + 2] - coords[r * 3 + 2];
            sdist[t] = sqrtf(dx * dx + dy * dy + dz * dz);
        } else {
            ss[t] = 0; sr[t] = -1; sdist[t] = 0.f;
        }
    }
    __syncthreads();

    // stage 1: gather + collapsed layer-1 + silu
    for (int i = tid; i < 128 * 32; i += 256) {
        int e = i >> 5, d4 = (i & 31) << 2;
        int rr = sr[e]; if (rr < 0) rr = 0;
        const float4 a = *(const float4*)(g_A + (size_t)ss[e] * D + d4);
        const float4 b = *(const float4*)(g_B + (size_t)rr    * D + d4);
        float dist = sdist[e];
        float4 o;
        o.x = silu_f(a.x + b.x + dist * sw1c[d4 + 0] + sb1[d4 + 0]);
        o.y = silu_f(a.y + b.y + dist * sw1c[d4 + 1] + sb1[d4 + 1]);
        o.z = silu_f(a.z + b.z + dist * sw1c[d4 + 2] + sb1[d4 + 2]);
        o.w = silu_f(a.w + b.w + dist * sw1c[d4 + 3] + sb1[d4 + 3]);
        *(float4*)&XE[e][d4] = o;
    }
    __syncthreads();

    // stage 2: layer-2 GEMM (weights streamed from L1-resident global)
    const int tx = tid & 15, ty = tid >> 4;
    u64 acc2[8][4];
    #pragma unroll
    for (int i = 0; i < 8; ++i)
        #pragma unroll
        for (int j = 0; j < 4; ++j) acc2[i][j] = 0ull;

    gemm_tile_g(XE, g_W2T, acc2, tx, ty);

    // epilogue: bias + silu + vectorized scatter-add
    const int db = tx * 4;
    #pragma unroll
    for (int i = 0; i < 8; ++i) {
        int e = (i < 4) ? (ty * 4 + i) : (64 + ty * 4 + i - 4);
        int r = sr[e];
        if (r < 0) continue;
        float* dst = g_agg + (size_t)r * D;
        float2 p0 = unpack2(acc2[i][0]), p1 = unpack2(acc2[i][1]);
        float2 p2 = unpack2(acc2[i][2]), p3 = unpack2(acc2[i][3]);
        red_v4(dst + db,
               silu_f(p0.x + sb2[db + 0]), silu_f(p0.y + sb2[db + 1]),
               silu_f(p1.x + sb2[db + 2]), silu_f(p1.y + sb2[db + 3]));
        red_v4(dst + 64 + db,
               silu_f(p2.x + sb2[64 + db + 0]), silu_f(p2.y + sb2[64 + db + 1]),
               silu_f(p3.x + sb2[64 + db + 2]), silu_f(p3.y + sb2[64 + db + 3]));
    }
}

// ----------------------------------------------------------------------------
// T = silu([h, agg] @ U1.T + c1)    (two K-phases: h @ U1a.T + agg @ U1b.T)
// ----------------------------------------------------------------------------
__global__ __launch_bounds__(256, 2)
void node_c1_kernel(const float* __restrict__ h, const float* __restrict__ c1, int N)
{
    extern __shared__ float sm[];
    float (*XE)[132] = (float (*)[132])sm;
    float* sc1 = sm + 128 * 132;

    const int tid = threadIdx.x;
    const int n0  = blockIdx.x * 128;
    if (tid < 128) sc1[tid] = c1[tid];

    const int tx = tid & 15, ty = tid >> 4;
    u64 acc2[8][4];
    #pragma unroll
    for (int i = 0; i < 8; ++i)
        #pragma unroll
        for (int j = 0; j < 4; ++j) acc2[i][j] = 0ull;

    for (int ph = 0; ph < 2; ++ph) {
        if (ph) __syncthreads();
        const float* src = ph ? g_agg : h;
        for (int i = tid; i < 128 * 32; i += 256) {
            int e = i >> 5, d4 = (i & 31) << 2;
            int n = n0 + e;
            float4 v = make_float4(0.f, 0.f, 0.f, 0.f);
            if (n < N) v = *(const float4*)(src + (size_t)n * D + d4);
            *(float4*)&XE[e][d4] = v;
        }
        __syncthreads();
        gemm_tile_g(XE, ph ? g_U1Tb : g_U1Ta, acc2, tx, ty);
    }

    const int db = tx * 4;
    #pragma unroll
    for (int i = 0; i < 8; ++i) {
        int e = (i < 4) ? (ty * 4 + i) : (64 + ty * 4 + i - 4);
        int n = n0 + e;
        if (n >= N) continue;
        float* dst = g_T + (size_t)n * D;
        float2 p0 = unpack2(acc2[i][0]), p1 = unpack2(acc2[i][1]);
        float2 p2 = unpack2(acc2[i][2]), p3 = unpack2(acc2[i][3]);
        *(float4*)(dst + db) = make_float4(
            silu_f(p0.x + sc1[db + 0]), silu_f(p0.y + sc1[db + 1]),
            silu_f(p1.x + sc1[db + 2]), silu_f(p1.y + sc1[db + 3]));
        *(float4*)(dst + 64 + db) = make_float4(
            silu_f(p2.x + sc1[64 + db + 0]), silu_f(p2.y + sc1[64 + db + 1]),
            silu_f(p3.x + sc1[64 + db + 2]), silu_f(p3.y + sc1[64 + db + 3]));
    }
}

// ----------------------------------------------------------------------------
// out = h + T @ U2.T + c2
// ----------------------------------------------------------------------------
__global__ __launch_bounds__(256, 2)
void node_c2_kernel(const float* __restrict__ h, const float* __restrict__ c2,
                    float* __restrict__ out, int N)
{
    extern __shared__ float sm[];
    float (*XE)[132] = (float (*)[132])sm;
    float* sc2 = sm + 128 * 132;

    const int tid = threadIdx.x;
    const int n0  = blockIdx.x * 128;
    if (tid < 128) sc2[tid] = c2[tid];

    for (int i = tid; i < 128 * 32; i += 256) {
        int e = i >> 5, d4 = (i & 31) << 2;
        int n = n0 + e;
        float4 v = make_float4(0.f, 0.f, 0.f, 0.f);
        if (n < N) v = *(const float4*)(g_T + (size_t)n * D + d4);
        *(float4*)&XE[e][d4] = v;
    }
    __syncthreads();

    const int tx = tid & 15, ty = tid >> 4;
    u64 acc2[8][4];
    #pragma unroll
    for (int i = 0; i < 8; ++i)
        #pragma unroll
        for (int j = 0; j < 4; ++j) acc2[i][j] = 0ull;

    gemm_tile_g(XE, g_U2T, acc2, tx, ty);

    const int db = tx * 4;
    #pragma unroll
    for (int i = 0; i < 8; ++i) {
        int e = (i < 4) ? (ty * 4 + i) : (64 + ty * 4 + i - 4);
        int n = n0 + e;
        if (n >= N) continue;
        const float* hp = h + (size_t)n * D;
        float* op = out + (size_t)n * D;
        float4 h0 = *(const float4*)(hp + db);
        float4 h1 = *(const float4*)(hp + 64 + db);
        float2 p0 = unpack2(acc2[i][0]), p1 = unpack2(acc2[i][1]);
        float2 p2 = unpack2(acc2[i][2]), p3 = unpack2(acc2[i][3]);
        *(float4*)(op + db) = make_float4(
            h0.x + p0.x + sc2[db + 0], h0.y + p0.y + sc2[db + 1],
            h0.z + p1.x + sc2[db + 2], h0.w + p1.y + sc2[db + 3]);
        *(float4*)(op + 64 + db) = make_float4(
            h1.x + p2.x + sc2[64 + db + 0], h1.y + p2.y + sc2[64 + db + 1],
            h1.z + p3.x + sc2[64 + db + 2], h1.w + p3.y + sc2[64 + db + 3]);
    }
}

// ----------------------------------------------------------------------------
extern "C" void kernel_launch(void* const* d_in, const int* in_sizes, int n_in,
                              void* d_out, int out_size)
{
    const float*     h      = (const float*)d_in[0];
    const float*     coords = (const float*)d_in[1];
    const void*      ei     = d_in[2];
    const float*     W1     = (const float*)d_in[3];
    const float*     b1     = (const float*)d_in[4];
    const float*     W2     = (const float*)d_in[5];
    const float*     b2     = (const float*)d_in[6];
    const float*     U1     = (const float*)d_in[7];
    const float*     c1     = (const float*)d_in[8];
    const float*     U2     = (const float*)d_in[9];
    const float*     c2     = (const float*)d_in[10];
    float*           out    = (float*)d_out;

    const int N = in_sizes[0] / D;
    const int E = in_sizes[2] / 2;

    const size_t SMEM_EDGE = (size_t)(128 * 132 + 4 * 128) * 4 + 2 * 128 * 4; // ~70.7 KB
    const size_t SMEM_NODE = (size_t)(128 * 132 + 128) * 4;                   // ~68.1 KB
    const size_t SMEM_AB   = (size_t)(128 * 132) * 4;                         // ~67.6 KB

    cudaFuncSetAttribute(edge_kernel,    cudaFuncAttributeMaxDynamicSharedMemorySize, (int)SMEM_EDGE);
    cudaFuncSetAttribute(nodeAB_kernel,  cudaFuncAttributeMaxDynamicSharedMemorySize, (int)SMEM_AB);
    cudaFuncSetAttribute(node_c1_kernel, cudaFuncAttributeMaxDynamicSharedMemorySize, (int)SMEM_NODE);
    cudaFuncSetAttribute(node_c2_kernel, cudaFuncAttributeMaxDynamicSharedMemorySize, (int)SMEM_NODE);

    const int nTiles = (N + 127) / 128;

    // 0) weight transposes (device-side symbol access) + dtype detect + zero agg
    transpose_all_kernel<<<dim3(4, 4, 6), dim3(32, 8)>>>(W1, W2, U1, U2);

    detect_idx_kernel<<<1, 256>>>((const int*)ei, E);

    int n4 = N * (D / 4);
    zero_agg_kernel<<<(n4 + 255) / 256, 256>>>(n4);

    // 1) per-node layer-1 precompute (A, B halves)
    nodeAB_kernel<<<dim3(nTiles, 2), 256, SMEM_AB>>>(h, N);

    // 2) edge MLP + scatter
    edge_kernel<<<(E + 127) / 128, 256, SMEM_EDGE>>>(coords, ei, W1, b1, b2, E);

    // 3) node update layer 1
    node_c1_kernel<<<nTiles, 256, SMEM_NODE>>>(h, c1, N);

    // 4) node update layer 2 + residual
    node_c2_kernel<<<nTiles, 256, SMEM_NODE>>>(h, c2, out, N);
}

// round 9
// speedup vs baseline: 1.0235x; 1.0235x over previous
#include <cuda_runtime.h>
#include <cstdint>

#define D 128
#define NMAX 50000

typedef unsigned long long u64;

// ---- scratch (static device globals; no allocations allowed) ----
__device__ float g_A  [(size_t)NMAX * D];   // h @ W1a.T
__device__ float g_B  [(size_t)NMAX * D];   // h @ W1b.T
__device__ float g_agg[(size_t)NMAX * D];   // scatter-add target
__device__ float g_T  [(size_t)NMAX * D];   // silu(u_in @ U1.T + c1)
__device__ int   g_is64;                    // edge_index dtype flag

// k-major weight copies: gWT[k*128 + d] = W[d][k]
__device__ float g_W1Ta[128 * 128];
__device__ float g_W1Tb[128 * 128];
__device__ float g_W2T [128 * 128];
__device__ float g_U1Ta[128 * 128];
__device__ float g_U1Tb[128 * 128];
__device__ float g_U2T [128 * 128];

__device__ __forceinline__ float silu_f(float v) {
    return v / (1.0f + __expf(-v));
}
__device__ __forceinline__ u64 pack2(float lo, float hi) {
    u64 r;
    asm("mov.b64 %0, {%1, %2};" : "=l"(r) : "f"(lo), "f"(hi));
    return r;
}
__device__ __forceinline__ float2 unpack2(u64 v) {
    float2 r;
    asm("mov.b64 {%0, %1}, %2;" : "=f"(r.x), "=f"(r.y) : "l"(v));
    return r;
}
__device__ __forceinline__ void ffma2(u64& d, u64 a, u64 b) {
    asm("fma.rn.f32x2 %0, %1, %2, %0;" : "+l"(d) : "l"(a), "l"(b));
}
__device__ __forceinline__ void red_v4(float* p, float a, float b, float c, float d) {
    asm volatile("red.global.add.v4.f32 [%0], {%1, %2, %3, %4};"
                 :: "l"(p), "f"(a), "f"(b), "f"(c), "f"(d) : "memory");
}
__device__ __forceinline__ void red_v2(float* p, float a, float b) {
    asm volatile("red.global.add.v2.f32 [%0], {%1, %2};"
                 :: "l"(p), "f"(a), "f"(b) : "memory");
}
__device__ __forceinline__ uint32_t f2tf32(float f) {
    uint32_t r;
    asm("cvt.rna.tf32.f32 %0, %1;" : "=r"(r) : "f"(f));
    return r;
}
// D(16x8) += A(16x8, tf32, row) * B(8x8, tf32, col)
__device__ __forceinline__ void mma_tf32(float (&c)[4],
                                         uint32_t a0, uint32_t a1, uint32_t a2, uint32_t a3,
                                         uint32_t b0, uint32_t b1)
{
    asm volatile(
        "mma.sync.aligned.m16n8k8.row.col.f32.tf32.tf32.f32 "
        "{%0,%1,%2,%3}, {%4,%5,%6,%7}, {%8,%9}, {%0,%1,%2,%3};"
        : "+f"(c[0]), "+f"(c[1]), "+f"(c[2]), "+f"(c[3])
        : "r"(a0), "r"(a1), "r"(a2), "r"(a3), "r"(b0), "r"(b1));
}

// ----------------------------------------------------------------------------
// All six 128x128 weight transposes; destination symbols referenced in DEVICE
// code. blockIdx.z selects; out[k*128 + d] = in[d*ldin + off + k].
// ----------------------------------------------------------------------------
__global__ void transpose_all_kernel(const float* __restrict__ W1,
                                     const float* __restrict__ W2,
                                     const float* __restrict__ U1,
                                     const float* __restrict__ U2)
{
    const float* in; float* out; int ldin, off;
    switch (blockIdx.z) {
        case 0: in = W1; out = g_W1Ta; ldin = 257; off = 0;   break;
        case 1: in = W1; out = g_W1Tb; ldin = 257; off = 128; break;
        case 2: in = W2; out = g_W2T;  ldin = 128; off = 0;   break;
        case 3: in = U1; out = g_U1Ta; ldin = 256; off = 0;   break;
        case 4: in = U1; out = g_U1Tb; ldin = 256; off = 128; break;
        default: in = U2; out = g_U2T; ldin = 128; off = 0;   break;
    }
    __shared__ float t[32][33];
    int kb = blockIdx.x * 32, db = blockIdx.y * 32;
    int tx = threadIdx.x, ty = threadIdx.y;
    for (int j = ty; j < 32; j += 8)
        t[j][tx] = in[(size_t)(db + j) * ldin + off + kb + tx];
    __syncthreads();
    for (int j = ty; j < 32; j += 8)
        out[(size_t)(kb + j) * 128 + db + tx] = t[tx][j];
}

// ----------------------------------------------------------------------------
__global__ void detect_idx_kernel(const int* __restrict__ ei32, int E)
{
    __shared__ int any_nz;
    if (threadIdx.x == 0) any_nz = 0;
    __syncthreads();
    int samples = min(1024, E);
    for (int i = threadIdx.x; i < samples; i += blockDim.x)
        if (ei32[2 * i + 1] != 0) any_nz = 1;
    __syncthreads();
    if (threadIdx.x == 0) g_is64 = (any_nz == 0) ? 1 : 0;
}

__device__ __forceinline__ void load_edge(const void* ei, int E, int e, int is64,
                                          int& s, int& r)
{
    if (is64) {
        s = (int)((const long long*)ei)[e];
        r = (int)((const long long*)ei)[(size_t)E + e];
    } else {
        s = ((const int*)ei)[e];
        r = ((const int*)ei)[E + e];
    }
}

// ----------------------------------------------------------------------------
// fp32x2 FFMA GEMM core (node kernels): [128x128] smem tile x k-major global W.
// ----------------------------------------------------------------------------
__device__ __forceinline__ void gemm_tile_g(const float (*__restrict__ XE)[132],
                                            const float* __restrict__ WG,
                                            u64 (&acc2)[8][4], int tx, int ty)
{
    const int eb = ty * 4, db = tx * 4;
    #pragma unroll 4
    for (int k = 0; k < 128; ++k) {
        const float* wr = WG + k * 128;
        ulonglong2 w0 = *(const ulonglong2*)(wr + db);
        ulonglong2 w1 = *(const ulonglong2*)(wr + 64 + db);
        u64 wv[4] = {w0.x, w0.y, w1.x, w1.y};
        u64 xa2[8];
        #pragma unroll
        for (int i = 0; i < 4; ++i) {
            float x0 = XE[eb + i][k];
            float x1 = XE[64 + eb + i][k];
            xa2[i]     = pack2(x0, x0);
            xa2[4 + i] = pack2(x1, x1);
        }
        #pragma unroll
        for (int i = 0; i < 8; ++i)
            #pragma unroll
            for (int jp = 0; jp < 4; ++jp)
                ffma2(acc2[i][jp], xa2[i], wv[jp]);
    }
}

// ----------------------------------------------------------------------------
__global__ void zero_agg_kernel(int n4) {
    int i = blockIdx.x * blockDim.x + threadIdx.x;
    if (i < n4) ((float4*)g_agg)[i] = make_float4(0.f, 0.f, 0.f, 0.f);
}

// ----------------------------------------------------------------------------
// A = h @ W1[:, :128].T ; B = h @ W1[:, 128:256].T   (blockIdx.y selects half)
// ----------------------------------------------------------------------------
__global__ __launch_bounds__(256, 2)
void nodeAB_kernel(const float* __restrict__ h, int N)
{
    extern __shared__ float sm[];
    float (*XE)[132] = (float (*)[132])sm;                 // 128 x 132

    const int tid  = threadIdx.x;
    const int n0   = blockIdx.x * 128;
    const int half = blockIdx.y;
    const float* WG = half ? g_W1Tb : g_W1Ta;

    for (int i = tid; i < 128 * 32; i += 256) {
        int e = i >> 5, d4 = (i & 31) << 2;
        int n = n0 + e;
        float4 v = make_float4(0.f, 0.f, 0.f, 0.f);
        if (n < N) v = *(const float4*)(h + (size_t)n * D + d4);
        *(float4*)&XE[e][d4] = v;
    }
    __syncthreads();

    const int tx = tid & 15, ty = tid >> 4;
    u64 acc2[8][4];
    #pragma unroll
    for (int i = 0; i < 8; ++i)
        #pragma unroll
        for (int j = 0; j < 4; ++j) acc2[i][j] = 0ull;

    gemm_tile_g(XE, WG, acc2, tx, ty);

    float* outp = half ? g_B : g_A;
    #pragma unroll
    for (int i = 0; i < 8; ++i) {
        int e = (i < 4) ? (ty * 4 + i) : (64 + ty * 4 + i - 4);
        int n = n0 + e;
        if (n >= N) continue;
        float2 p0 = unpack2(acc2[i][0]), p1 = unpack2(acc2[i][1]);
        float2 p2 = unpack2(acc2[i][2]), p3 = unpack2(acc2[i][3]);
        *(float4*)(outp + (size_t)n * D + tx * 4)      = make_float4(p0.x, p0.y, p1.x, p1.y);
        *(float4*)(outp + (size_t)n * D + 64 + tx * 4) = make_float4(p2.x, p2.y, p3.x, p3.y);
    }
}

// ----------------------------------------------------------------------------
// Edge kernel — TENSOR CORE version (mma.sync tf32).
// 128 edges/block, 256 threads (8 warps); warp w owns rows 16w..16w+15.
//   stage 0: W2T (k-major) -> smem tf32 (stride 136: conflict-free B frags)
//   stage 1: gather + collapsed layer-1 + silu -> XE (tf32-rounded, stride 132)
//   stage 2: 16 k-steps x 16 n-tiles m16n8k8 HMMA
//   epilogue: bias + silu + red.global.add.v2 scatter
// ----------------------------------------------------------------------------
__global__ __launch_bounds__(256, 1)
void edge_kernel(const float* __restrict__ coords,
                 const void* __restrict__ ei,
                 const float* __restrict__ W1,
                 const float* __restrict__ b1,
                 const float* __restrict__ b2,
                 int E)
{
    extern __shared__ float sm[];
    float (*XE)[132] = (float (*)[132])sm;                       // 128 x 132
    float (*WT)[136] = (float (*)[136])(sm + 128 * 132);         // 128 x 136
    float* sw1c  = sm + 128 * 132 + 128 * 136;                   // 128
    float* sb1   = sw1c + 128;                                   // 128
    float* sb2   = sb1 + 128;                                    // 128
    float* sdist = sb2 + 128;                                    // 128
    int*   sr    = (int*)(sdist + 128);                          // 128
    int*   ss    = sr + 128;                                     // 128

    const int tid = threadIdx.x;
    const int e0  = blockIdx.x * 128;
    const int is64 = g_is64;

    // stage 0: weights -> smem as tf32 (k-major, stride 136)
    for (int i = tid; i < 128 * 128; i += 256) {
        int k = i >> 7, n = i & 127;
        WT[k][n] = __uint_as_float(f2tf32(g_W2T[i]));
    }
    if (tid < 128) {
        sb1[tid]  = b1[tid];
        sb2[tid]  = b2[tid];
        sw1c[tid] = W1[tid * 257 + 256];
    } else {
        int t = tid - 128;
        int e = e0 + t;
        if (e < E) {
            int s, r;
            load_edge(ei, E, e, is64, s, r);
            ss[t] = s;
            sr[t] = r;
            float dx = coords[s * 3 + 0] - coords[r * 3 + 0];
            float dy = coords[s * 3 + 1] - coords[r * 3 + 1];
            float dz = coords[s * 3 + 2] - coords[r * 3 + 2];
            sdist[t] = sqrtf(dx * dx + dy * dy + dz * dz);
        } else {
            ss[t] = 0; sr[t] = -1; sdist[t] = 0.f;
        }
    }
    __syncthreads();

    // stage 1: gather + collapsed layer-1 + silu (tf32-rounded into XE)
    for (int i = tid; i < 128 * 32; i += 256) {
        int e = i >> 5, d4 = (i & 31) << 2;
        int rr = sr[e]; if (rr < 0) rr = 0;
        const float4 a = *(const float4*)(g_A + (size_t)ss[e] * D + d4);
        const float4 b = *(const float4*)(g_B + (size_t)rr    * D + d4);
        float dist = sdist[e];
        float4 o;
        o.x = silu_f(a.x + b.x + dist * sw1c[d4 + 0] + sb1[d4 + 0]);
        o.y = silu_f(a.y + b.y + dist * sw1c[d4 + 1] + sb1[d4 + 1]);
        o.z = silu_f(a.z + b.z + dist * sw1c[d4 + 2] + sb1[d4 + 2]);
        o.w = silu_f(a.w + b.w + dist * sw1c[d4 + 3] + sb1[d4 + 3]);
        float4 t4;
        t4.x = __uint_as_float(f2tf32(o.x));
        t4.y = __uint_as_float(f2tf32(o.y));
        t4.z = __uint_as_float(f2tf32(o.z));
        t4.w = __uint_as_float(f2tf32(o.w));
        *(float4*)&XE[e][d4] = t4;
    }
    __syncthreads();

    // stage 2: tensor-core GEMM
    const int warp = tid >> 5, lane = tid & 31;
    const int gid = lane >> 2, tig = lane & 3;
    const int rowBase = warp * 16;

    float acc[16][4];
    #pragma unroll
    for (int nt = 0; nt < 16; ++nt)
        #pragma unroll
        for (int j = 0; j < 4; ++j) acc[nt][j] = 0.f;

    #pragma unroll 2
    for (int k0 = 0; k0 < 128; k0 += 8) {
        uint32_t a0 = __float_as_uint(XE[rowBase + gid    ][k0 + tig]);
        uint32_t a1 = __float_as_uint(XE[rowBase + gid + 8][k0 + tig]);
        uint32_t a2 = __float_as_uint(XE[rowBase + gid    ][k0 + tig + 4]);
        uint32_t a3 = __float_as_uint(XE[rowBase + gid + 8][k0 + tig + 4]);
        #pragma unroll
        for (int nt = 0; nt < 16; ++nt) {
            uint32_t b0 = __float_as_uint(WT[k0 + tig    ][nt * 8 + gid]);
            uint32_t b1 = __float_as_uint(WT[k0 + tig + 4][nt * 8 + gid]);
            mma_tf32(acc[nt], a0, a1, a2, a3, b0, b1);
        }
    }

    // epilogue: bias + silu + vectorized scatter (C frag: rows gid/gid+8, col pairs)
    #pragma unroll
    for (int half = 0; half < 2; ++half) {
        int erow = rowBase + gid + half * 8;
        int r = sr[erow];
        if (r < 0) continue;
        float* dst = g_agg + (size_t)r * D;
        #pragma unroll
        for (int nt = 0; nt < 16; ++nt) {
            int col = nt * 8 + tig * 2;
            float v0 = silu_f(acc[nt][half * 2 + 0] + sb2[col]);
            float v1 = silu_f(acc[nt][half * 2 + 1] + sb2[col + 1]);
            red_v2(dst + col, v0, v1);
        }
    }
}

// ----------------------------------------------------------------------------
// T = silu([h, agg] @ U1.T + c1)    (two K-phases: h @ U1a.T + agg @ U1b.T)
// ----------------------------------------------------------------------------
__global__ __launch_bounds__(256, 2)
void node_c1_kernel(const float* __restrict__ h, const float* __restrict__ c1, int N)
{
    extern __shared__ float sm[];
    float (*XE)[132] = (float (*)[132])sm;
    float* sc1 = sm + 128 * 132;

    const int tid = threadIdx.x;
    const int n0  = blockIdx.x * 128;
    if (tid < 128) sc1[tid] = c1[tid];

    const int tx = tid & 15, ty = tid >> 4;
    u64 acc2[8][4];
    #pragma unroll
    for (int i = 0; i < 8; ++i)
        #pragma unroll
        for (int j = 0; j < 4; ++j) acc2[i][j] = 0ull;

    for (int ph = 0; ph < 2; ++ph) {
        if (ph) __syncthreads();
        const float* src = ph ? g_agg : h;
        for (int i = tid; i < 128 * 32; i += 256) {
            int e = i >> 5, d4 = (i & 31) << 2;
            int n = n0 + e;
            float4 v = make_float4(0.f, 0.f, 0.f, 0.f);
            if (n < N) v = *(const float4*)(src + (size_t)n * D + d4);
            *(float4*)&XE[e][d4] = v;
        }
        __syncthreads();
        gemm_tile_g(XE, ph ? g_U1Tb : g_U1Ta, acc2, tx, ty);
    }

    const int db = tx * 4;
    #pragma unroll
    for (int i = 0; i < 8; ++i) {
        int e = (i < 4) ? (ty * 4 + i) : (64 + ty * 4 + i - 4);
        int n = n0 + e;
        if (n >= N) continue;
        float* dst = g_T + (size_t)n * D;
        float2 p0 = unpack2(acc2[i][0]), p1 = unpack2(acc2[i][1]);
        float2 p2 = unpack2(acc2[i][2]), p3 = unpack2(acc2[i][3]);
        *(float4*)(dst + db) = make_float4(
            silu_f(p0.x + sc1[db + 0]), silu_f(p0.y + sc1[db + 1]),
            silu_f(p1.x + sc1[db + 2]), silu_f(p1.y + sc1[db + 3]));
        *(float4*)(dst + 64 + db) = make_float4(
            silu_f(p2.x + sc1[64 + db + 0]), silu_f(p2.y + sc1[64 + db + 1]),
            silu_f(p3.x + sc1[64 + db + 2]), silu_f(p3.y + sc1[64 + db + 3]));
    }
}

// ----------------------------------------------------------------------------
// out = h + T @ U2.T + c2
// ----------------------------------------------------------------------------
__global__ __launch_bounds__(256, 2)
void node_c2_kernel(const float* __restrict__ h, const float* __restrict__ c2,
                    float* __restrict__ out, int N)
{
    extern __shared__ float sm[];
    float (*XE)[132] = (float (*)[132])sm;
    float* sc2 = sm + 128 * 132;

    const int tid = threadIdx.x;
    const int n0  = blockIdx.x * 128;
    if (tid < 128) sc2[tid] = c2[tid];

    for (int i = tid; i < 128 * 32; i += 256) {
        int e = i >> 5, d4 = (i & 31) << 2;
        int n = n0 + e;
        float4 v = make_float4(0.f, 0.f, 0.f, 0.f);
        if (n < N) v = *(const float4*)(g_T + (size_t)n * D + d4);
        *(float4*)&XE[e][d4] = v;
    }
    __syncthreads();

    const int tx = tid & 15, ty = tid >> 4;
    u64 acc2[8][4];
    #pragma unroll
    for (int i = 0; i < 8; ++i)
        #pragma unroll
        for (int j = 0; j < 4; ++j) acc2[i][j] = 0ull;

    gemm_tile_g(XE, g_U2T, acc2, tx, ty);

    const int db = tx * 4;
    #pragma unroll
    for (int i = 0; i < 8; ++i) {
        int e = (i < 4) ? (ty * 4 + i) : (64 + ty * 4 + i - 4);
        int n = n0 + e;
        if (n >= N) continue;
        const float* hp = h + (size_t)n * D;
        float* op = out + (size_t)n * D;
        float4 h0 = *(const float4*)(hp + db);
        float4 h1 = *(const float4*)(hp + 64 + db);
        float2 p0 = unpack2(acc2[i][0]), p1 = unpack2(acc2[i][1]);
        float2 p2 = unpack2(acc2[i][2]), p3 = unpack2(acc2[i][3]);
        *(float4*)(op + db) = make_float4(
            h0.x + p0.x + sc2[db + 0], h0.y + p0.y + sc2[db + 1],
            h0.z + p1.x + sc2[db + 2], h0.w + p1.y + sc2[db + 3]);
        *(float4*)(op + 64 + db) = make_float4(
            h1.x + p2.x + sc2[64 + db + 0], h1.y + p2.y + sc2[64 + db + 1],
            h1.z + p3.x + sc2[64 + db + 2], h1.w + p3.y + sc2[64 + db + 3]);
    }
}

// ----------------------------------------------------------------------------
extern "C" void kernel_launch(void* const* d_in, const int* in_sizes, int n_in,
                              void* d_out, int out_size)
{
    const float*     h      = (const float*)d_in[0];
    const float*     coords = (const float*)d_in[1];
    const void*      ei     = d_in[2];
    const float*     W1     = (const float*)d_in[3];
    const float*     b1     = (const float*)d_in[4];
    const float*     W2     = (const float*)d_in[5];
    const float*     b2     = (const float*)d_in[6];
    const float*     U1     = (const float*)d_in[7];
    const float*     c1     = (const float*)d_in[8];
    const float*     U2     = (const float*)d_in[9];
    const float*     c2     = (const float*)d_in[10];
    float*           out    = (float*)d_out;

    const int N = in_sizes[0] / D;
    const int E = in_sizes[2] / 2;

    const size_t SMEM_EDGE = (size_t)(128 * 132 + 128 * 136 + 4 * 128) * 4
                           + 2 * 128 * 4;                     // ~137 KB
    const size_t SMEM_NODE = (size_t)(128 * 132 + 128) * 4;   // ~66.5 KB
    const size_t SMEM_AB   = (size_t)(128 * 132) * 4;         // ~66 KB

    cudaFuncSetAttribute(edge_kernel,    cudaFuncAttributeMaxDynamicSharedMemorySize, (int)SMEM_EDGE);
    cudaFuncSetAttribute(nodeAB_kernel,  cudaFuncAttributeMaxDynamicSharedMemorySize, (int)SMEM_AB);
    cudaFuncSetAttribute(node_c1_kernel, cudaFuncAttributeMaxDynamicSharedMemorySize, (int)SMEM_NODE);
    cudaFuncSetAttribute(node_c2_kernel, cudaFuncAttributeMaxDynamicSharedMemorySize, (int)SMEM_NODE);

    const int nTiles = (N + 127) / 128;

    // 0) weight transposes + dtype detect + zero agg
    transpose_all_kernel<<<dim3(4, 4, 6), dim3(32, 8)>>>(W1, W2, U1, U2);

    detect_idx_kernel<<<1, 256>>>((const int*)ei, E);

    int n4 = N * (D / 4);
    zero_agg_kernel<<<(n4 + 255) / 256, 256>>>(n4);

    // 1) per-node layer-1 precompute (A, B halves)
    nodeAB_kernel<<<dim3(nTiles, 2), 256, SMEM_AB>>>(h, N);

    // 2) edge MLP + scatter (tensor-core GEMM)
    edge_kernel<<<(E + 127) / 128, 256, SMEM_EDGE>>>(coords, ei, W1, b1, b2, E);

    // 3) node update layer 1
    node_c1_kernel<<<nTiles, 256, SMEM_NODE>>>(h, c1, N);

    // 4) node update layer 2 + residual
    node_c2_kernel<<<nTiles, 256, SMEM_NODE>>>(h, c2, out, N);
}

// round 10
// speedup vs baseline: 1.1867x; 1.1595x over previous
#include <cuda_runtime.h>
#include <cstdint>

#define D 128
#define NMAX 50000

typedef unsigned long long u64;

// ---- scratch (static device globals; no allocations allowed) ----
__device__ float g_A  [(size_t)NMAX * D];   // h @ W1a.T
__device__ float g_B  [(size_t)NMAX * D];   // h @ W1b.T
__device__ float g_agg[(size_t)NMAX * D];   // scatter-add target
__device__ float g_T  [(size_t)NMAX * D];   // silu(u_in @ U1.T + c1)
__device__ int   g_is64;                    // edge_index dtype flag

// k-major weight copies: gWT[k*128 + d] = W[d][k]   (FFMA node kernels)
__device__ float g_W1Ta[128 * 128];
__device__ float g_W1Tb[128 * 128];
__device__ float g_U1Ta[128 * 128];
__device__ float g_U1Tb[128 * 128];
__device__ float g_U2T [128 * 128];
// W2 in per-thread B-fragment order, tf32-rounded:
//   g_W2F[k*128 + gid*16 + nt] = tf32( W2[nt*8+gid][k] )
__device__ float g_W2F [128 * 128];

__device__ __forceinline__ float silu_f(float v) {
    return v / (1.0f + __expf(-v));
}
__device__ __forceinline__ u64 pack2(float lo, float hi) {
    u64 r;
    asm("mov.b64 %0, {%1, %2};" : "=l"(r) : "f"(lo), "f"(hi));
    return r;
}
__device__ __forceinline__ float2 unpack2(u64 v) {
    float2 r;
    asm("mov.b64 {%0, %1}, %2;" : "=f"(r.x), "=f"(r.y) : "l"(v));
    return r;
}
__device__ __forceinline__ void ffma2(u64& d, u64 a, u64 b) {
    asm("fma.rn.f32x2 %0, %1, %2, %0;" : "+l"(d) : "l"(a), "l"(b));
}
__device__ __forceinline__ void red_v2(float* p, float a, float b) {
    asm volatile("red.global.add.v2.f32 [%0], {%1, %2};"
                 :: "l"(p), "f"(a), "f"(b) : "memory");
}
__device__ __forceinline__ uint32_t f2tf32(float f) {
    uint32_t r;
    asm("cvt.rna.tf32.f32 %0, %1;" : "=r"(r) : "f"(f));
    return r;
}
// D(16x8) += A(16x8, tf32, row) * B(8x8, tf32, col)
__device__ __forceinline__ void mma_tf32(float (&c)[4],
                                         uint32_t a0, uint32_t a1, uint32_t a2, uint32_t a3,
                                         uint32_t b0, uint32_t b1)
{
    asm volatile(
        "mma.sync.aligned.m16n8k8.row.col.f32.tf32.tf32.f32 "
        "{%0,%1,%2,%3}, {%4,%5,%6,%7}, {%8,%9}, {%0,%1,%2,%3};"
        : "+f"(c[0]), "+f"(c[1]), "+f"(c[2]), "+f"(c[3])
        : "r"(a0), "r"(a1), "r"(a2), "r"(a3), "r"(b0), "r"(b1));
}

// ----------------------------------------------------------------------------
// Five 128x128 weight transposes (node-kernel weights); device-side symbols.
// out[k*128 + d] = in[d*ldin + off + k].
// ----------------------------------------------------------------------------
__global__ void transpose_all_kernel(const float* __restrict__ W1,
                                     const float* __restrict__ U1,
                                     const float* __restrict__ U2)
{
    const float* in; float* out; int ldin, off;
    switch (blockIdx.z) {
        case 0: in = W1; out = g_W1Ta; ldin = 257; off = 0;   break;
        case 1: in = W1; out = g_W1Tb; ldin = 257; off = 128; break;
        case 2: in = U1; out = g_U1Ta; ldin = 256; off = 0;   break;
        case 3: in = U1; out = g_U1Tb; ldin = 256; off = 128; break;
        default: in = U2; out = g_U2T; ldin = 128; off = 0;   break;
    }
    __shared__ float t[32][33];
    int kb = blockIdx.x * 32, db = blockIdx.y * 32;
    int tx = threadIdx.x, ty = threadIdx.y;
    for (int j = ty; j < 32; j += 8)
        t[j][tx] = in[(size_t)(db + j) * ldin + off + kb + tx];
    __syncthreads();
    for (int j = ty; j < 32; j += 8)
        out[(size_t)(kb + j) * 128 + db + tx] = t[tx][j];
}

// ----------------------------------------------------------------------------
// W2 -> B-fragment order, tf32-rounded (one-time).
// ----------------------------------------------------------------------------
__global__ void w2f_kernel(const float* __restrict__ W2)
{
    int i = blockIdx.x * 256 + threadIdx.x;          // i < 16384
    int k = i >> 7, c = i & 127;
    int gid = c >> 4, nt = c & 15;
    int d = nt * 8 + gid;
    g_W2F[i] = __uint_as_float(f2tf32(W2[d * 128 + k]));
}

// ----------------------------------------------------------------------------
__global__ void detect_idx_kernel(const int* __restrict__ ei32, int E)
{
    __shared__ int any_nz;
    if (threadIdx.x == 0) any_nz = 0;
    __syncthreads();
    int samples = min(1024, E);
    for (int i = threadIdx.x; i < samples; i += blockDim.x)
        if (ei32[2 * i + 1] != 0) any_nz = 1;
    __syncthreads();
    if (threadIdx.x == 0) g_is64 = (any_nz == 0) ? 1 : 0;
}

__device__ __forceinline__ void load_edge(const void* ei, int E, int e, int is64,
                                          int& s, int& r)
{
    if (is64) {
        s = (int)((const long long*)ei)[e];
        r = (int)((const long long*)ei)[(size_t)E + e];
    } else {
        s = ((const int*)ei)[e];
        r = ((const int*)ei)[E + e];
    }
}

// ----------------------------------------------------------------------------
// fp32x2 FFMA GEMM core (node kernels): [128x128] smem tile x k-major global W.
// ----------------------------------------------------------------------------
__device__ __forceinline__ void gemm_tile_g(const float (*__restrict__ XE)[132],
                                            const float* __restrict__ WG,
                                            u64 (&acc2)[8][4], int tx, int ty)
{
    const int eb = ty * 4, db = tx * 4;
    #pragma unroll 4
    for (int k = 0; k < 128; ++k) {
        const float* wr = WG + k * 128;
        ulonglong2 w0 = *(const ulonglong2*)(wr + db);
        ulonglong2 w1 = *(const ulonglong2*)(wr + 64 + db);
        u64 wv[4] = {w0.x, w0.y, w1.x, w1.y};
        u64 xa2[8];
        #pragma unroll
        for (int i = 0; i < 4; ++i) {
            float x0 = XE[eb + i][k];
            float x1 = XE[64 + eb + i][k];
            xa2[i]     = pack2(x0, x0);
            xa2[4 + i] = pack2(x1, x1);
        }
        #pragma unroll
        for (int i = 0; i < 8; ++i)
            #pragma unroll
            for (int jp = 0; jp < 4; ++jp)
                ffma2(acc2[i][jp], xa2[i], wv[jp]);
    }
}

// ----------------------------------------------------------------------------
__global__ void zero_agg_kernel(int n4) {
    int i = blockIdx.x * blockDim.x + threadIdx.x;
    if (i < n4) ((float4*)g_agg)[i] = make_float4(0.f, 0.f, 0.f, 0.f);
}

// ----------------------------------------------------------------------------
// A = h @ W1[:, :128].T ; B = h @ W1[:, 128:256].T   (blockIdx.y selects half)
// ----------------------------------------------------------------------------
__global__ __launch_bounds__(256, 2)
void nodeAB_kernel(const float* __restrict__ h, int N)
{
    extern __shared__ float sm[];
    float (*XE)[132] = (float (*)[132])sm;                 // 128 x 132

    const int tid  = threadIdx.x;
    const int n0   = blockIdx.x * 128;
    const int half = blockIdx.y;
    const float* WG = half ? g_W1Tb : g_W1Ta;

    for (int i = tid; i < 128 * 32; i += 256) {
        int e = i >> 5, d4 = (i & 31) << 2;
        int n = n0 + e;
        float4 v = make_float4(0.f, 0.f, 0.f, 0.f);
        if (n < N) v = *(const float4*)(h + (size_t)n * D + d4);
        *(float4*)&XE[e][d4] = v;
    }
    __syncthreads();

    const int tx = tid & 15, ty = tid >> 4;
    u64 acc2[8][4];
    #pragma unroll
    for (int i = 0; i < 8; ++i)
        #pragma unroll
        for (int j = 0; j < 4; ++j) acc2[i][j] = 0ull;

    gemm_tile_g(XE, WG, acc2, tx, ty);

    float* outp = half ? g_B : g_A;
    #pragma unroll
    for (int i = 0; i < 8; ++i) {
        int e = (i < 4) ? (ty * 4 + i) : (64 + ty * 4 + i - 4);
        int n = n0 + e;
        if (n >= N) continue;
        float2 p0 = unpack2(acc2[i][0]), p1 = unpack2(acc2[i][1]);
        float2 p2 = unpack2(acc2[i][2]), p3 = unpack2(acc2[i][3]);
        *(float4*)(outp + (size_t)n * D + tx * 4)      = make_float4(p0.x, p0.y, p1.x, p1.y);
        *(float4*)(outp + (size_t)n * D + 64 + tx * 4) = make_float4(p2.x, p2.y, p3.x, p3.y);
    }
}

// ----------------------------------------------------------------------------
// Edge kernel — tf32 mma, 128 edges/block, 256 threads, 2 CTAs/SM.
//   stage 1: gather + collapsed layer-1 + silu -> XE (tf32-rounded)
//   stage 2: A-frags from XE smem; B-frags from g_W2F via contiguous LDG.128
//            (L1-resident); 16 k-steps x 16 n-tiles m16n8k8.
//   epilogue: bias + silu + red.global.add.v2 scatter
// ----------------------------------------------------------------------------
__global__ __launch_bounds__(256, 2)
void edge_kernel(const float* __restrict__ coords,
                 const void* __restrict__ ei,
                 const float* __restrict__ W1,
                 const float* __restrict__ b1,
                 const float* __restrict__ b2,
                 int E)
{
    extern __shared__ float sm[];
    float (*XE)[132] = (float (*)[132])sm;                   // 128 x 132
    float* sw1c  = sm + 128 * 132;                           // 128
    float* sb1   = sw1c + 128;                               // 128
    float* sb2   = sb1 + 128;                                // 128
    float* sdist = sb2 + 128;                                // 128
    int*   sr    = (int*)(sdist + 128);                      // 128
    int*   ss    = sr + 128;                                 // 128

    const int tid = threadIdx.x;
    const int e0  = blockIdx.x * 128;
    const int is64 = g_is64;

    if (tid < 128) {
        sb1[tid]  = b1[tid];
        sb2[tid]  = b2[tid];
        sw1c[tid] = W1[tid * 257 + 256];
    } else {
        int t = tid - 128;
        int e = e0 + t;
        if (e < E) {
            int s, r;
            load_edge(ei, E, e, is64, s, r);
            ss[t] = s;
            sr[t] = r;
            float dx = coords[s * 3 + 0] - coords[r * 3 + 0];
            float dy = coords[s * 3 + 1] - coords[r * 3 + 1];
            float dz = coords[s * 3 + 2] - coords[r * 3 + 2];
            sdist[t] = sqrtf(dx * dx + dy * dy + dz * dz);
        } else {
            ss[t] = 0; sr[t] = -1; sdist[t] = 0.f;
        }
    }
    __syncthreads();

    // stage 1: gather + collapsed layer-1 + silu (tf32-rounded into XE)
    for (int i = tid; i < 128 * 32; i += 256) {
        int e = i >> 5, d4 = (i & 31) << 2;
        int rr = sr[e]; if (rr < 0) rr = 0;
        const float4 a = *(const float4*)(g_A + (size_t)ss[e] * D + d4);
        const float4 b = *(const float4*)(g_B + (size_t)rr    * D + d4);
        float dist = sdist[e];
        float4 o;
        o.x = __uint_as_float(f2tf32(silu_f(a.x + b.x + dist * sw1c[d4 + 0] + sb1[d4 + 0])));
        o.y = __uint_as_float(f2tf32(silu_f(a.y + b.y + dist * sw1c[d4 + 1] + sb1[d4 + 1])));
        o.z = __uint_as_float(f2tf32(silu_f(a.z + b.z + dist * sw1c[d4 + 2] + sb1[d4 + 2])));
        o.w = __uint_as_float(f2tf32(silu_f(a.w + b.w + dist * sw1c[d4 + 3] + sb1[d4 + 3])));
        *(float4*)&XE[e][d4] = o;
    }
    __syncthreads();

    // stage 2: tensor-core GEMM
    const int warp = tid >> 5, lane = tid & 31;
    const int gid = lane >> 2, tig = lane & 3;
    const int rowBase = warp * 16;

    float acc[16][4];
    #pragma unroll
    for (int nt = 0; nt < 16; ++nt)
        #pragma unroll
        for (int j = 0; j < 4; ++j) acc[nt][j] = 0.f;

    const float* wf0base = g_W2F + (size_t)gid * 16;
    #pragma unroll 1
    for (int k0 = 0; k0 < 128; k0 += 8) {
        uint32_t a0 = __float_as_uint(XE[rowBase + gid    ][k0 + tig]);
        uint32_t a1 = __float_as_uint(XE[rowBase + gid + 8][k0 + tig]);
        uint32_t a2 = __float_as_uint(XE[rowBase + gid    ][k0 + tig + 4]);
        uint32_t a3 = __float_as_uint(XE[rowBase + gid + 8][k0 + tig + 4]);
        // B-frags: 16 contiguous floats per (k, gid) in g_W2F
        const float* wf0 = wf0base + (size_t)(k0 + tig) * 128;
        const float* wf1 = wf0 + 4 * 128;
        float4 b0v[4], b1v[4];
        #pragma unroll
        for (int q = 0; q < 4; ++q) {
            b0v[q] = *(const float4*)(wf0 + q * 4);
            b1v[q] = *(const float4*)(wf1 + q * 4);
        }
        const float* b0a = (const float*)b0v;
        const float* b1a = (const float*)b1v;
        #pragma unroll
        for (int nt = 0; nt < 16; ++nt)
            mma_tf32(acc[nt], a0, a1, a2, a3,
                     __float_as_uint(b0a[nt]), __float_as_uint(b1a[nt]));
    }

    // epilogue: bias + silu + vectorized scatter (C frag: rows gid/gid+8, col pairs)
    #pragma unroll
    for (int half = 0; half < 2; ++half) {
        int erow = rowBase + gid + half * 8;
        int r = sr[erow];
        if (r < 0) continue;
        float* dst = g_agg + (size_t)r * D;
        #pragma unroll
        for (int nt = 0; nt < 16; ++nt) {
            int col = nt * 8 + tig * 2;
            float v0 = silu_f(acc[nt][half * 2 + 0] + sb2[col]);
            float v1 = silu_f(acc[nt][half * 2 + 1] + sb2[col + 1]);
            red_v2(dst + col, v0, v1);
        }
    }
}

// ----------------------------------------------------------------------------
// T = silu([h, agg] @ U1.T + c1)    (two K-phases: h @ U1a.T + agg @ U1b.T)
// ----------------------------------------------------------------------------
__global__ __launch_bounds__(256, 2)
void node_c1_kernel(const float* __restrict__ h, const float* __restrict__ c1, int N)
{
    extern __shared__ float sm[];
    float (*XE)[132] = (float (*)[132])sm;
    float* sc1 = sm + 128 * 132;

    const int tid = threadIdx.x;
    const int n0  = blockIdx.x * 128;
    if (tid < 128) sc1[tid] = c1[tid];

    const int tx = tid & 15, ty = tid >> 4;
    u64 acc2[8][4];
    #pragma unroll
    for (int i = 0; i < 8; ++i)
        #pragma unroll
        for (int j = 0; j < 4; ++j) acc2[i][j] = 0ull;

    for (int ph = 0; ph < 2; ++ph) {
        if (ph) __syncthreads();
        const float* src = ph ? g_agg : h;
        for (int i = tid; i < 128 * 32; i += 256) {
            int e = i >> 5, d4 = (i & 31) << 2;
            int n = n0 + e;
            float4 v = make_float4(0.f, 0.f, 0.f, 0.f);
            if (n < N) v = *(const float4*)(src + (size_t)n * D + d4);
            *(float4*)&XE[e][d4] = v;
        }
        __syncthreads();
        gemm_tile_g(XE, ph ? g_U1Tb : g_U1Ta, acc2, tx, ty);
    }

    const int db = tx * 4;
    #pragma unroll
    for (int i = 0; i < 8; ++i) {
        int e = (i < 4) ? (ty * 4 + i) : (64 + ty * 4 + i - 4);
        int n = n0 + e;
        if (n >= N) continue;
        float* dst = g_T + (size_t)n * D;
        float2 p0 = unpack2(acc2[i][0]), p1 = unpack2(acc2[i][1]);
        float2 p2 = unpack2(acc2[i][2]), p3 = unpack2(acc2[i][3]);
        *(float4*)(dst + db) = make_float4(
            silu_f(p0.x + sc1[db + 0]), silu_f(p0.y + sc1[db + 1]),
            silu_f(p1.x + sc1[db + 2]), silu_f(p1.y + sc1[db + 3]));
        *(float4*)(dst + 64 + db) = make_float4(
            silu_f(p2.x + sc1[64 + db + 0]), silu_f(p2.y + sc1[64 + db + 1]),
            silu_f(p3.x + sc1[64 + db + 2]), silu_f(p3.y + sc1[64 + db + 3]));
    }
}

// ----------------------------------------------------------------------------
// out = h + T @ U2.T + c2
// ----------------------------------------------------------------------------
__global__ __launch_bounds__(256, 2)
void node_c2_kernel(const float* __restrict__ h, const float* __restrict__ c2,
                    float* __restrict__ out, int N)
{
    extern __shared__ float sm[];
    float (*XE)[132] = (float (*)[132])sm;
    float* sc2 = sm + 128 * 132;

    const int tid = threadIdx.x;
    const int n0  = blockIdx.x * 128;
    if (tid < 128) sc2[tid] = c2[tid];

    for (int i = tid; i < 128 * 32; i += 256) {
        int e = i >> 5, d4 = (i & 31) << 2;
        int n = n0 + e;
        float4 v = make_float4(0.f, 0.f, 0.f, 0.f);
        if (n < N) v = *(const float4*)(g_T + (size_t)n * D + d4);
        *(float4*)&XE[e][d4] = v;
    }
    __syncthreads();

    const int tx = tid & 15, ty = tid >> 4;
    u64 acc2[8][4];
    #pragma unroll
    for (int i = 0; i < 8; ++i)
        #pragma unroll
        for (int j = 0; j < 4; ++j) acc2[i][j] = 0ull;

    gemm_tile_g(XE, g_U2T, acc2, tx, ty);

    const int db = tx * 4;
    #pragma unroll
    for (int i = 0; i < 8; ++i) {
        int e = (i < 4) ? (ty * 4 + i) : (64 + ty * 4 + i - 4);
        int n = n0 + e;
        if (n >= N) continue;
        const float* hp = h + (size_t)n * D;
        float* op = out + (size_t)n * D;
        float4 h0 = *(const float4*)(hp + db);
        float4 h1 = *(const float4*)(hp + 64 + db);
        float2 p0 = unpack2(acc2[i][0]), p1 = unpack2(acc2[i][1]);
        float2 p2 = unpack2(acc2[i][2]), p3 = unpack2(acc2[i][3]);
        *(float4*)(op + db) = make_float4(
            h0.x + p0.x + sc2[db + 0], h0.y + p0.y + sc2[db + 1],
            h0.z + p1.x + sc2[db + 2], h0.w + p1.y + sc2[db + 3]);
        *(float4*)(op + 64 + db) = make_float4(
            h1.x + p2.x + sc2[64 + db + 0], h1.y + p2.y + sc2[64 + db + 1],
            h1.z + p3.x + sc2[64 + db + 2], h1.w + p3.y + sc2[64 + db + 3]);
    }
}

// ----------------------------------------------------------------------------
extern "C" void kernel_launch(void* const* d_in, const int* in_sizes, int n_in,
                              void* d_out, int out_size)
{
    const float*     h      = (const float*)d_in[0];
    const float*     coords = (const float*)d_in[1];
    const void*      ei     = d_in[2];
    const float*     W1     = (const float*)d_in[3];
    const float*     b1     = (const float*)d_in[4];
    const float*     W2     = (const float*)d_in[5];
    const float*     b2     = (const float*)d_in[6];
    const float*     U1     = (const float*)d_in[7];
    const float*     c1     = (const float*)d_in[8];
    const float*     U2     = (const float*)d_in[9];
    const float*     c2     = (const float*)d_in[10];
    float*           out    = (float*)d_out;

    const int N = in_sizes[0] / D;
    const int E = in_sizes[2] / 2;

    const size_t SMEM_EDGE = (size_t)(128 * 132 + 4 * 128) * 4 + 2 * 128 * 4; // ~70.7 KB
    const size_t SMEM_NODE = (size_t)(128 * 132 + 128) * 4;                   // ~66.5 KB
    const size_t SMEM_AB   = (size_t)(128 * 132) * 4;                         // ~66 KB

    cudaFuncSetAttribute(edge_kernel,    cudaFuncAttributeMaxDynamicSharedMemorySize, (int)SMEM_EDGE);
    cudaFuncSetAttribute(nodeAB_kernel,  cudaFuncAttributeMaxDynamicSharedMemorySize, (int)SMEM_AB);
    cudaFuncSetAttribute(node_c1_kernel, cudaFuncAttributeMaxDynamicSharedMemorySize, (int)SMEM_NODE);
    cudaFuncSetAttribute(node_c2_kernel, cudaFuncAttributeMaxDynamicSharedMemorySize, (int)SMEM_NODE);

    const int nTiles = (N + 127) / 128;

    // 0) weight prep (transposes + W2 fragment layout) + dtype detect + zero agg
    transpose_all_kernel<<<dim3(4, 4, 5), dim3(32, 8)>>>(W1, U1, U2);
    w2f_kernel<<<64, 256>>>(W2);
    detect_idx_kernel<<<1, 256>>>((const int*)ei, E);

    int n4 = N * (D / 4);
    zero_agg_kernel<<<(n4 + 255) / 256, 256>>>(n4);

    // 1) per-node layer-1 precompute (A, B halves)
    nodeAB_kernel<<<dim3(nTiles, 2), 256, SMEM_AB>>>(h, N);

    // 2) edge MLP + scatter (tensor-core GEMM, 2 CTAs/SM)
    edge_kernel<<<(E + 127) / 128, 256, SMEM_EDGE>>>(coords, ei, W1, b1, b2, E);

    // 3) node update layer 1
    node_c1_kernel<<<nTiles, 256, SMEM_NODE>>>(h, c1, N);

    // 4) node update layer 2 + residual
    node_c2_kernel<<<nTiles, 256, SMEM_NODE>>>(h, c2, out, N);
}

// round 11
// speedup vs baseline: 1.2708x; 1.0708x over previous
#include <cuda_runtime.h>
#include <cstdint>

#define D 128
#define NMAX 50000

typedef unsigned long long u64;

// ---- scratch (static device globals; no allocations allowed) ----
__device__ float g_A  [(size_t)NMAX * D];   // h @ W1a.T
__device__ float g_B  [(size_t)NMAX * D];   // h @ W1b.T
__device__ float g_agg[(size_t)NMAX * D];   // scatter-add target
__device__ float g_T  [(size_t)NMAX * D];   // silu(u_in @ U1.T + c1)
__device__ int   g_is64;                    // edge_index dtype flag

// Weights in per-thread B-fragment order, tf32-rounded:
//   g_F_X[k*128 + gid*16 + nt] = tf32( Wsrc[(nt*8+gid)*ldin + off + k] )
__device__ float g_F_W1a[128 * 128];
__device__ float g_F_W1b[128 * 128];
__device__ float g_F_W2 [128 * 128];
__device__ float g_F_U1a[128 * 128];
__device__ float g_F_U1b[128 * 128];
__device__ float g_F_U2 [128 * 128];

__device__ __forceinline__ float silu_f(float v) {
    return v / (1.0f + __expf(-v));
}
__device__ __forceinline__ void red_v2(float* p, float a, float b) {
    asm volatile("red.global.add.v2.f32 [%0], {%1, %2};"
                 :: "l"(p), "f"(a), "f"(b) : "memory");
}
__device__ __forceinline__ uint32_t f2tf32(float f) {
    uint32_t r;
    asm("cvt.rna.tf32.f32 %0, %1;" : "=r"(r) : "f"(f));
    return r;
}
// D(16x8) += A(16x8, tf32, row) * B(8x8, tf32, col)
__device__ __forceinline__ void mma_tf32(float (&c)[4],
                                         uint32_t a0, uint32_t a1, uint32_t a2, uint32_t a3,
                                         uint32_t b0, uint32_t b1)
{
    asm volatile(
        "mma.sync.aligned.m16n8k8.row.col.f32.tf32.tf32.f32 "
        "{%0,%1,%2,%3}, {%4,%5,%6,%7}, {%8,%9}, {%0,%1,%2,%3};"
        : "+f"(c[0]), "+f"(c[1]), "+f"(c[2]), "+f"(c[3])
        : "r"(a0), "r"(a1), "r"(a2), "r"(a3), "r"(b0), "r"(b1));
}

// ----------------------------------------------------------------------------
// All six weight matrices -> B-fragment order, tf32 (one-time).
// blockIdx.y selects the matrix.
// ----------------------------------------------------------------------------
__global__ void wfrag_kernel(const float* __restrict__ W1,
                             const float* __restrict__ W2,
                             const float* __restrict__ U1,
                             const float* __restrict__ U2)
{
    const float* in; float* out; int ldin, off;
    switch (blockIdx.y) {
        case 0: in = W1; out = g_F_W1a; ldin = 257; off = 0;   break;
        case 1: in = W1; out = g_F_W1b; ldin = 257; off = 128; break;
        case 2: in = W2; out = g_F_W2;  ldin = 128; off = 0;   break;
        case 3: in = U1; out = g_F_U1a; ldin = 256; off = 0;   break;
        case 4: in = U1; out = g_F_U1b; ldin = 256; off = 128; break;
        default: in = U2; out = g_F_U2; ldin = 128; off = 0;   break;
    }
    int i = blockIdx.x * 256 + threadIdx.x;          // i < 16384
    int k = i >> 7, c = i & 127;
    int gid = c >> 4, nt = c & 15;
    int d = nt * 8 + gid;
    out[i] = __uint_as_float(f2tf32(in[(size_t)d * ldin + off + k]));
}

// ----------------------------------------------------------------------------
__global__ void detect_idx_kernel(const int* __restrict__ ei32, int E)
{
    __shared__ int any_nz;
    if (threadIdx.x == 0) any_nz = 0;
    __syncthreads();
    int samples = min(1024, E);
    for (int i = threadIdx.x; i < samples; i += blockDim.x)
        if (ei32[2 * i + 1] != 0) any_nz = 1;
    __syncthreads();
    if (threadIdx.x == 0) g_is64 = (any_nz == 0) ? 1 : 0;
}

__device__ __forceinline__ void load_edge(const void* ei, int E, int e, int is64,
                                          int& s, int& r)
{
    if (is64) {
        s = (int)((const long long*)ei)[e];
        r = (int)((const long long*)ei)[(size_t)E + e];
    } else {
        s = ((const int*)ei)[e];
        r = ((const int*)ei)[E + e];
    }
}

__global__ void zero_agg_kernel(int n4) {
    int i = blockIdx.x * blockDim.x + threadIdx.x;
    if (i < n4) ((float4*)g_agg)[i] = make_float4(0.f, 0.f, 0.f, 0.f);
}

// ----------------------------------------------------------------------------
// Shared tf32-mma tile core: XE [128 x 132] smem (tf32-rounded activations),
// WF = fragment-ordered weights in global (L1-resident). Each of 8 warps owns
// a 16-row stripe; 16 k-steps x 16 n-tiles of m16n8k8.
// ----------------------------------------------------------------------------
__device__ __forceinline__ void mma_tile(const float (*__restrict__ XE)[132],
                                         const float* __restrict__ WF,
                                         float (&acc)[16][4],
                                         int rowBase, int gid, int tig)
{
    const float* wfb = WF + (size_t)gid * 16;
    #pragma unroll 1
    for (int k0 = 0; k0 < 128; k0 += 8) {
        uint32_t a0 = __float_as_uint(XE[rowBase + gid    ][k0 + tig]);
        uint32_t a1 = __float_as_uint(XE[rowBase + gid + 8][k0 + tig]);
        uint32_t a2 = __float_as_uint(XE[rowBase + gid    ][k0 + tig + 4]);
        uint32_t a3 = __float_as_uint(XE[rowBase + gid + 8][k0 + tig + 4]);
        const float* wf0 = wfb + (size_t)(k0 + tig) * 128;
        const float* wf1 = wf0 + 4 * 128;
        float4 b0v[4], b1v[4];
        #pragma unroll
        for (int q = 0; q < 4; ++q) {
            b0v[q] = *(const float4*)(wf0 + q * 4);
            b1v[q] = *(const float4*)(wf1 + q * 4);
        }
        const float* b0a = (const float*)b0v;
        const float* b1a = (const float*)b1v;
        #pragma unroll
        for (int nt = 0; nt < 16; ++nt)
            mma_tf32(acc[nt], a0, a1, a2, a3,
                     __float_as_uint(b0a[nt]), __float_as_uint(b1a[nt]));
    }
}

// Stage a [128 x 128] tile from global into XE with tf32 rounding.
__device__ __forceinline__ void stage_tile(const float* __restrict__ src, int n0, int N,
                                           float (*__restrict__ XE)[132], int tid)
{
    for (int i = tid; i < 128 * 32; i += 256) {
        int e = i >> 5, d4 = (i & 31) << 2;
        int n = n0 + e;
        float4 v = make_float4(0.f, 0.f, 0.f, 0.f);
        if (n < N) v = *(const float4*)(src + (size_t)n * D + d4);
        float4 o;
        o.x = __uint_as_float(f2tf32(v.x));
        o.y = __uint_as_float(f2tf32(v.y));
        o.z = __uint_as_float(f2tf32(v.z));
        o.w = __uint_as_float(f2tf32(v.w));
        *(float4*)&XE[e][d4] = o;
    }
}

// ----------------------------------------------------------------------------
// A = h @ W1a.T ; B = h @ W1b.T   (blockIdx.y selects half)  — tf32 mma
// ----------------------------------------------------------------------------
__global__ __launch_bounds__(256, 2)
void nodeAB_kernel(const float* __restrict__ h, int N)
{
    extern __shared__ float sm[];
    float (*XE)[132] = (float (*)[132])sm;                 // 128 x 132

    const int tid  = threadIdx.x;
    const int n0   = blockIdx.x * 128;
    const int half = blockIdx.y;

    stage_tile(h, n0, N, XE, tid);
    __syncthreads();

    const int warp = tid >> 5, lane = tid & 31;
    const int gid = lane >> 2, tig = lane & 3;
    const int rowBase = warp * 16;

    float acc[16][4];
    #pragma unroll
    for (int nt = 0; nt < 16; ++nt)
        #pragma unroll
        for (int j = 0; j < 4; ++j) acc[nt][j] = 0.f;

    mma_tile(XE, half ? g_F_W1b : g_F_W1a, acc, rowBase, gid, tig);

    float* outp = half ? g_B : g_A;
    #pragma unroll
    for (int hh = 0; hh < 2; ++hh) {
        int n = n0 + rowBase + gid + hh * 8;
        if (n >= N) continue;
        float* dst = outp + (size_t)n * D;
        #pragma unroll
        for (int nt = 0; nt < 16; ++nt) {
            int col = nt * 8 + tig * 2;
            *(float2*)(dst + col) = make_float2(acc[nt][hh * 2], acc[nt][hh * 2 + 1]);
        }
    }
}

// ----------------------------------------------------------------------------
// Edge kernel — tf32 mma, 128 edges/block, 256 threads, 2 CTAs/SM.
// ----------------------------------------------------------------------------
__global__ __launch_bounds__(256, 2)
void edge_kernel(const float* __restrict__ coords,
                 const void* __restrict__ ei,
                 const float* __restrict__ W1,
                 const float* __restrict__ b1,
                 const float* __restrict__ b2,
                 int E)
{
    extern __shared__ float sm[];
    float (*XE)[132] = (float (*)[132])sm;                   // 128 x 132
    float* sw1c  = sm + 128 * 132;                           // 128
    float* sb1   = sw1c + 128;                               // 128
    float* sb2   = sb1 + 128;                                // 128
    float* sdist = sb2 + 128;                                // 128
    int*   sr    = (int*)(sdist + 128);                      // 128
    int*   ss    = sr + 128;                                 // 128

    const int tid = threadIdx.x;
    const int e0  = blockIdx.x * 128;
    const int is64 = g_is64;

    if (tid < 128) {
        sb1[tid]  = b1[tid];
        sb2[tid]  = b2[tid];
        sw1c[tid] = W1[tid * 257 + 256];
    } else {
        int t = tid - 128;
        int e = e0 + t;
        if (e < E) {
            int s, r;
            load_edge(ei, E, e, is64, s, r);
            ss[t] = s;
            sr[t] = r;
            float dx = coords[s * 3 + 0] - coords[r * 3 + 0];
            float dy = coords[s * 3 + 1] - coords[r * 3 + 1];
            float dz = coords[s * 3 + 2] - coords[r * 3 + 2];
            sdist[t] = sqrtf(dx * dx + dy * dy + dz * dz);
        } else {
            ss[t] = 0; sr[t] = -1; sdist[t] = 0.f;
        }
    }
    __syncthreads();

    // gather + collapsed layer-1 + silu (tf32-rounded into XE)
    for (int i = tid; i < 128 * 32; i += 256) {
        int e = i >> 5, d4 = (i & 31) << 2;
        int rr = sr[e]; if (rr < 0) rr = 0;
        const float4 a = *(const float4*)(g_A + (size_t)ss[e] * D + d4);
        const float4 b = *(const float4*)(g_B + (size_t)rr    * D + d4);
        float dist = sdist[e];
        float4 o;
        o.x = __uint_as_float(f2tf32(silu_f(a.x + b.x + dist * sw1c[d4 + 0] + sb1[d4 + 0])));
        o.y = __uint_as_float(f2tf32(silu_f(a.y + b.y + dist * sw1c[d4 + 1] + sb1[d4 + 1])));
        o.z = __uint_as_float(f2tf32(silu_f(a.z + b.z + dist * sw1c[d4 + 2] + sb1[d4 + 2])));
        o.w = __uint_as_float(f2tf32(silu_f(a.w + b.w + dist * sw1c[d4 + 3] + sb1[d4 + 3])));
        *(float4*)&XE[e][d4] = o;
    }
    __syncthreads();

    const int warp = tid >> 5, lane = tid & 31;
    const int gid = lane >> 2, tig = lane & 3;
    const int rowBase = warp * 16;

    float acc[16][4];
    #pragma unroll
    for (int nt = 0; nt < 16; ++nt)
        #pragma unroll
        for (int j = 0; j < 4; ++j) acc[nt][j] = 0.f;

    mma_tile(XE, g_F_W2, acc, rowBase, gid, tig);

    // epilogue: bias + silu + vectorized scatter
    #pragma unroll
    for (int hh = 0; hh < 2; ++hh) {
        int erow = rowBase + gid + hh * 8;
        int r = sr[erow];
        if (r < 0) continue;
        float* dst = g_agg + (size_t)r * D;
        #pragma unroll
        for (int nt = 0; nt < 16; ++nt) {
            int col = nt * 8 + tig * 2;
            float v0 = silu_f(acc[nt][hh * 2 + 0] + sb2[col]);
            float v1 = silu_f(acc[nt][hh * 2 + 1] + sb2[col + 1]);
            red_v2(dst + col, v0, v1);
        }
    }
}

// ----------------------------------------------------------------------------
// T = silu([h, agg] @ U1.T + c1)   — tf32 mma, two accumulating K-phases
// ----------------------------------------------------------------------------
__global__ __launch_bounds__(256, 2)
void node_c1_kernel(const float* __restrict__ h, const float* __restrict__ c1, int N)
{
    extern __shared__ float sm[];
    float (*XE)[132] = (float (*)[132])sm;
    float* sc1 = sm + 128 * 132;

    const int tid = threadIdx.x;
    const int n0  = blockIdx.x * 128;
    if (tid < 128) sc1[tid] = c1[tid];

    const int warp = tid >> 5, lane = tid & 31;
    const int gid = lane >> 2, tig = lane & 3;
    const int rowBase = warp * 16;

    float acc[16][4];
    #pragma unroll
    for (int nt = 0; nt < 16; ++nt)
        #pragma unroll
        for (int j = 0; j < 4; ++j) acc[nt][j] = 0.f;

    stage_tile(h, n0, N, XE, tid);
    __syncthreads();
    mma_tile(XE, g_F_U1a, acc, rowBase, gid, tig);
    __syncthreads();
    stage_tile(g_agg, n0, N, XE, tid);
    __syncthreads();
    mma_tile(XE, g_F_U1b, acc, rowBase, gid, tig);

    #pragma unroll
    for (int hh = 0; hh < 2; ++hh) {
        int n = n0 + rowBase + gid + hh * 8;
        if (n >= N) continue;
        float* dst = g_T + (size_t)n * D;
        #pragma unroll
        for (int nt = 0; nt < 16; ++nt) {
            int col = nt * 8 + tig * 2;
            float v0 = silu_f(acc[nt][hh * 2 + 0] + sc1[col]);
            float v1 = silu_f(acc[nt][hh * 2 + 1] + sc1[col + 1]);
            *(float2*)(dst + col) = make_float2(v0, v1);
        }
    }
}

// ----------------------------------------------------------------------------
// out = h + T @ U2.T + c2   — tf32 mma
// ----------------------------------------------------------------------------
__global__ __launch_bounds__(256, 2)
void node_c2_kernel(const float* __restrict__ h, const float* __restrict__ c2,
                    float* __restrict__ out, int N)
{
    extern __shared__ float sm[];
    float (*XE)[132] = (float (*)[132])sm;
    float* sc2 = sm + 128 * 132;

    const int tid = threadIdx.x;
    const int n0  = blockIdx.x * 128;
    if (tid < 128) sc2[tid] = c2[tid];

    stage_tile(g_T, n0, N, XE, tid);
    __syncthreads();

    const int warp = tid >> 5, lane = tid & 31;
    const int gid = lane >> 2, tig = lane & 3;
    const int rowBase = warp * 16;

    float acc[16][4];
    #pragma unroll
    for (int nt = 0; nt < 16; ++nt)
        #pragma unroll
        for (int j = 0; j < 4; ++j) acc[nt][j] = 0.f;

    mma_tile(XE, g_F_U2, acc, rowBase, gid, tig);

    #pragma unroll
    for (int hh = 0; hh < 2; ++hh) {
        int n = n0 + rowBase + gid + hh * 8;
        if (n >= N) continue;
        const float* hp = h + (size_t)n * D;
        float* op = out + (size_t)n * D;
        #pragma unroll
        for (int nt = 0; nt < 16; ++nt) {
            int col = nt * 8 + tig * 2;
            float2 hv = *(const float2*)(hp + col);
            float v0 = hv.x + acc[nt][hh * 2 + 0] + sc2[col];
            float v1 = hv.y + acc[nt][hh * 2 + 1] + sc2[col + 1];
            *(float2*)(op + col) = make_float2(v0, v1);
        }
    }
}

// ----------------------------------------------------------------------------
extern "C" void kernel_launch(void* const* d_in, const int* in_sizes, int n_in,
                              void* d_out, int out_size)
{
    const float*     h      = (const float*)d_in[0];
    const float*     coords = (const float*)d_in[1];
    const void*      ei     = d_in[2];
    const float*     W1     = (const float*)d_in[3];
    const float*     b1     = (const float*)d_in[4];
    const float*     W2     = (const float*)d_in[5];
    const float*     b2     = (const float*)d_in[6];
    const float*     U1     = (const float*)d_in[7];
    const float*     c1     = (const float*)d_in[8];
    const float*     U2     = (const float*)d_in[9];
    const float*     c2     = (const float*)d_in[10];
    float*           out    = (float*)d_out;

    const int N = in_sizes[0] / D;
    const int E = in_sizes[2] / 2;

    const size_t SMEM_EDGE = (size_t)(128 * 132 + 4 * 128) * 4 + 2 * 128 * 4; // ~70.7 KB
    const size_t SMEM_NODE = (size_t)(128 * 132 + 128) * 4;                   // ~66.5 KB
    const size_t SMEM_AB   = (size_t)(128 * 132) * 4;                         // ~66 KB

    cudaFuncSetAttribute(edge_kernel,    cudaFuncAttributeMaxDynamicSharedMemorySize, (int)SMEM_EDGE);
    cudaFuncSetAttribute(nodeAB_kernel,  cudaFuncAttributeMaxDynamicSharedMemorySize, (int)SMEM_AB);
    cudaFuncSetAttribute(node_c1_kernel, cudaFuncAttributeMaxDynamicSharedMemorySize, (int)SMEM_NODE);
    cudaFuncSetAttribute(node_c2_kernel, cudaFuncAttributeMaxDynamicSharedMemorySize, (int)SMEM_NODE);

    const int nTiles = (N + 127) / 128;

    // 0) weight fragment prep + dtype detect + zero agg
    wfrag_kernel<<<dim3(64, 6), 256>>>(W1, W2, U1, U2);
    detect_idx_kernel<<<1, 256>>>((const int*)ei, E);

    int n4 = N * (D / 4);
    zero_agg_kernel<<<(n4 + 255) / 256, 256>>>(n4);

    // 1) per-node layer-1 precompute (A, B halves)
    nodeAB_kernel<<<dim3(nTiles, 2), 256, SMEM_AB>>>(h, N);

    // 2) edge MLP + scatter
    edge_kernel<<<(E + 127) / 128, 256, SMEM_EDGE>>>(coords, ei, W1, b1, b2, E);

    // 3) node update layer 1
    node_c1_kernel<<<nTiles, 256, SMEM_NODE>>>(h, c1, N);

    // 4) node update layer 2 + residual
    node_c2_kernel<<<nTiles, 256, SMEM_NODE>>>(h, c2, out, N);
}